// round 16
// baseline (speedup 1.0000x reference)
#include <cuda_runtime.h>

#define B_SZ 8192
#define K_SZ 25
#define L_SZ 25
#define NCELL 256
#define NPBLK 128                 // prologue blocks (partials per l)
#define BN_EPS 1e-5f

typedef unsigned long long u64;

__device__ float g_part[4][L_SZ][NPBLK];       // [sum,sumsq,min,max][l][blk]
__device__ float g_lpA[L_SZ], g_lpC[L_SZ];     // u = fma(x, A, C)  (written by build k==0)
__device__ float2 g_table[L_SZ * NCELL * K_SZ];// [l][cell][k] = {alpha*f0, alpha*df}

// ---------- packed f32x2 helpers ----------
__device__ __forceinline__ u64 pack2(float a, float b) {
    u64 r;
    asm("mov.b64 %0, {%1, %2};" : "=l"(r) : "r"(__float_as_uint(a)), "r"(__float_as_uint(b)));
    return r;
}
__device__ __forceinline__ u64 dup2(float a) { return pack2(a, a); }
__device__ __forceinline__ float2 unpack2(u64 v) {
    unsigned lo, hi;
    asm("mov.b64 {%0, %1}, %2;" : "=r"(lo), "=r"(hi) : "l"(v));
    return make_float2(__uint_as_float(lo), __uint_as_float(hi));
}
__device__ __forceinline__ u64 ffma2(u64 a, u64 b, u64 c) {
    u64 d;
    asm("fma.rn.f32x2 %0, %1, %2, %3;" : "=l"(d) : "l"(a), "l"(b), "l"(c));
    return d;
}
__device__ __forceinline__ u64 relu2(u64 v) {
    float2 f = unpack2(v);
    return pack2(fmaxf(f.x, 0.f), fmaxf(f.y, 0.f));
}

// ---------- kernel 1: per-block stats partials (no atomics, no memset) ----------
__global__ void __launch_bounds__(128) prologue_kernel(const float* __restrict__ x)
{
    __shared__ float t[64][27];
    __shared__ float ps[4][32], pq[4][32], pmn[4][32], pmx[4][32];
    const int tid  = threadIdx.x;
    const int blk  = blockIdx.x;
    const int base = blk * 64;

    #pragma unroll
    for (int i = tid; i < 64 * L_SZ; i += 128) {
        int r = i / L_SZ, c = i - r * L_SZ;
        t[r][c] = x[base * L_SZ + i];
    }
    __syncthreads();

    {
        const int c = tid & 31, g = tid >> 5;
        float s = 0.f, q = 0.f, mn = 3.0e38f, mx = -3.0e38f;
        if (c < L_SZ) {
            #pragma unroll
            for (int r = g; r < 64; r += 4) {
                float v = t[r][c];
                s += v;
                q = fmaf(v, v, q);
                mn = fminf(mn, v);
                mx = fmaxf(mx, v);
            }
        }
        ps[g][c] = s; pq[g][c] = q; pmn[g][c] = mn; pmx[g][c] = mx;
    }
    __syncthreads();
    if (tid < L_SZ) {
        g_part[0][tid][blk] = ps[0][tid] + ps[1][tid] + ps[2][tid] + ps[3][tid];
        g_part[1][tid][blk] = pq[0][tid] + pq[1][tid] + pq[2][tid] + pq[3][tid];
        g_part[2][tid][blk] = fminf(fminf(pmn[0][tid], pmn[1][tid]), fminf(pmn[2][tid], pmn[3][tid]));
        g_part[3][tid][blk] = fmaxf(fmaxf(pmx[0][tid], pmx[1][tid]), fmaxf(pmx[2][tid], pmx[3][tid]));
    }
}

// ---------- kernel 2: reduce partials (in-block) + tabulate net, layout [l][cell][k] ----------
__global__ void __launch_bounds__(128) build_kernel(
    const float* __restrict__ gamma, const float* __restrict__ bn_bias,
    const float* __restrict__ W1, const float* __restrict__ b1,
    const float* __restrict__ W2, const float* __restrict__ b2,
    const float* __restrict__ W3, const float* __restrict__ b3,
    const float* __restrict__ W4, const float* __restrict__ b4,
    const float* __restrict__ alpha)
{
    __shared__ __align__(16) u64 sw1[8], sb1[8], sw2[64], sb2[8], sw3[48], sb3[6], sw4[6];
    __shared__ u64 sb4;
    __shared__ float nodes[NCELL + 2];
    __shared__ float4 red[128];
    __shared__ float sparam[2];     // {xnmin, h}

    const int l = blockIdx.x, k = blockIdx.y, tid = threadIdx.x;
    const int nb = k * L_SZ + l;

    // --- per-l stats reduction (identical order in every block for this l) ---
    red[tid] = make_float4(g_part[0][l][tid], g_part[1][l][tid],
                           g_part[2][l][tid], g_part[3][l][tid]);
    __syncthreads();
    #pragma unroll
    for (int s = 64; s > 0; s >>= 1) {
        if (tid < s) {
            float4 a = red[tid], b = red[tid + s];
            red[tid] = make_float4(a.x + b.x, a.y + b.y,
                                   fminf(a.z, b.z), fmaxf(a.w, b.w));
        }
        __syncthreads();
    }
    if (tid == 0) {
        float4 r = red[0];
        float mean = r.x * (1.f / (float)B_SZ);
        float var  = r.y * (1.f / (float)B_SZ) - mean * mean;
        float sc   = gamma[l] * rsqrtf(var + BN_EPS);
        float sh   = bn_bias[l] - mean * sc;
        float a1 = fmaf(sc, r.z, sh), a2 = fmaf(sc, r.w, sh);
        float xnmin = fminf(a1, a2), xnmax = fmaxf(a1, a2);
        float range = xnmax - xnmin;
        sparam[0] = xnmin;
        sparam[1] = range / (float)NCELL;
        if (k == 0) {
            float inv_h = (float)NCELL / range;
            g_lpA[l] = sc * inv_h;
            g_lpC[l] = (sh - xnmin) * inv_h;
        }
    }

    // --- weight load (overlaps with reduction above via separate smem) ---
    if (tid < 8)  sw1[tid] = dup2(W1[nb * 8 + tid]);
    if (tid < 8)  sb1[tid] = dup2(b1[nb * 8 + tid]);
    if (tid < 64) sw2[tid] = dup2(W2[nb * 64 + tid]);
    if (tid < 8)  sb2[tid] = dup2(b2[nb * 8 + tid]);
    if (tid < 48) sw3[tid] = dup2(W3[nb * 48 + tid]);
    if (tid < 6)  sb3[tid] = dup2(b3[nb * 6 + tid]);
    if (tid < 6)  sw4[tid] = dup2(W4[nb * 6 + tid]);
    if (tid == 0) sb4 = dup2(b4[nb]);
    __syncthreads();

    const float xnmin = sparam[0];
    const float h     = sparam[1];

    // evaluate node pairs (2i, 2i+1), packed f32x2
    for (int i = tid; i < NCELL / 2 + 1; i += 128) {
        float x0 = fmaf((float)(2 * i), h, xnmin);
        u64 xn = pack2(x0, x0 + h);

        u64 h1[8];
        #pragma unroll
        for (int j = 0; j < 8; ++j) h1[j] = relu2(ffma2(xn, sw1[j], sb1[j]));
        u64 h2[8];
        #pragma unroll
        for (int j = 0; j < 8; ++j) {
            u64 a = sb2[j];
            #pragma unroll
            for (int q = 0; q < 8; ++q) a = ffma2(h1[q], sw2[j * 8 + q], a);
            h2[j] = relu2(a);
        }
        u64 h3[6];
        #pragma unroll
        for (int j = 0; j < 6; ++j) {
            u64 a = sb3[j];
            #pragma unroll
            for (int q = 0; q < 8; ++q) a = ffma2(h2[q], sw3[j * 8 + q], a);
            h3[j] = relu2(a);
        }
        u64 f = sb4;
        #pragma unroll
        for (int j = 0; j < 6; ++j) f = ffma2(h3[j], sw4[j], f);

        float2 fv = unpack2(f);
        int n0 = 2 * i;
        if (n0 <= NCELL)     nodes[n0] = fv.x;
        if (n0 + 1 <= NCELL) nodes[n0 + 1] = fv.y;
    }
    __syncthreads();

    const float al = alpha[l * K_SZ + k];
    for (int i = tid; i < NCELL; i += 128) {
        float f0 = nodes[i], f1 = nodes[i + 1];
        g_table[(l * NCELL + i) * K_SZ + k] = make_float2(al * f0, al * (f1 - f0));
    }
}

// ---------- kernel 3: warp-per-sample eval, shuffle precomputed offset+frac ----------
__global__ void __launch_bounds__(128) eval_kernel(
    const float* __restrict__ x,
    const float* __restrict__ beta, float* __restrict__ out)
{
    const int tid  = threadIdx.x;
    const int lane = tid & 31;
    const int warp = tid >> 5;
    const int b    = blockIdx.x * 4 + warp;       // one sample per warp

    // lane l owns feature l: compute its table offset + frac once
    int   off_own  = 0;
    float frac_own = 0.f;
    if (lane < L_SZ) {
        float u = fmaf(x[b * L_SZ + lane], g_lpA[lane], g_lpC[lane]);
        int idx = __float2int_rd(u);
        idx = min(max(idx, 0), NCELL - 1);
        frac_own = u - (float)idx;
        off_own  = (lane * NCELL + idx) * K_SZ;
    }

    float acc0 = (lane < K_SZ) ? beta[lane] : 0.f;
    float acc1 = 0.f, acc2 = 0.f, acc3 = 0.f;

    #pragma unroll
    for (int l = 0; l < L_SZ; ++l) {
        int   off  = __shfl_sync(0xFFFFFFFFu, off_own, l);
        float frac = __shfl_sync(0xFFFFFFFFu, frac_own, l);
        if (lane < K_SZ) {
            float2 td = g_table[off + lane];      // 200B contiguous per warp
            float v = fmaf(frac, td.y, td.x);
            if ((l & 3) == 0) acc0 += v;
            else if ((l & 3) == 1) acc1 += v;
            else if ((l & 3) == 2) acc2 += v;
            else acc3 += v;
        }
    }

    if (lane < K_SZ) out[b * K_SZ + lane] = ((acc0 + acc1) + (acc2 + acc3));
}

extern "C" void kernel_launch(void* const* d_in, const int* in_sizes, int n_in,
                              void* d_out, int out_size) {
    const float* x      = (const float*)d_in[0];
    const float* gamma  = (const float*)d_in[1];
    const float* bnb    = (const float*)d_in[2];
    const float* W1     = (const float*)d_in[3];
    const float* b1     = (const float*)d_in[4];
    const float* W2     = (const float*)d_in[5];
    const float* b2     = (const float*)d_in[6];
    const float* W3     = (const float*)d_in[7];
    const float* b3     = (const float*)d_in[8];
    const float* W4     = (const float*)d_in[9];
    const float* b4     = (const float*)d_in[10];
    const float* alpha  = (const float*)d_in[11];
    const float* beta   = (const float*)d_in[12];
    float* out = (float*)d_out;

    prologue_kernel<<<NPBLK, 128>>>(x);
    build_kernel<<<dim3(L_SZ, K_SZ), 128>>>(gamma, bnb, W1, b1, W2, b2, W3, b3, W4, b4, alpha);
    eval_kernel<<<B_SZ / 4, 128>>>(x, beta, out);
}

// round 17
// speedup vs baseline: 1.0769x; 1.0769x over previous
#include <cuda_runtime.h>

#define B_SZ 8192
#define K_SZ 25
#define L_SZ 25
#define NCELL 256
#define KPAD 32
#define NPBLK 512                 // prologue blocks (16 rows each)
#define BN_EPS 1e-5f

typedef unsigned long long u64;

__device__ float g_part[4][L_SZ][NPBLK];       // [sum,sumsq,min,max][l][blk] (no reset needed)
__device__ float g_lpA[L_SZ], g_lpC[L_SZ];     // u = fma(x, A, C)
__device__ float g_lpXmin[L_SZ], g_lpH[L_SZ];  // xn-grid origin/step
__device__ __align__(256) float2 g_table[L_SZ * NCELL * KPAD]; // [l][cell][kpad]

// ---------- packed f32x2 helpers ----------
__device__ __forceinline__ u64 pack2(float a, float b) {
    u64 r;
    asm("mov.b64 %0, {%1, %2};" : "=l"(r) : "r"(__float_as_uint(a)), "r"(__float_as_uint(b)));
    return r;
}
__device__ __forceinline__ u64 dup2(float a) { return pack2(a, a); }
__device__ __forceinline__ float2 unpack2(u64 v) {
    unsigned lo, hi;
    asm("mov.b64 {%0, %1}, %2;" : "=r"(lo), "=r"(hi) : "l"(v));
    return make_float2(__uint_as_float(lo), __uint_as_float(hi));
}
__device__ __forceinline__ u64 ffma2(u64 a, u64 b, u64 c) {
    u64 d;
    asm("fma.rn.f32x2 %0, %1, %2, %3;" : "=l"(d) : "l"(a), "l"(b), "l"(c));
    return d;
}
__device__ __forceinline__ u64 relu2(u64 v) {
    float2 f = unpack2(v);
    return pack2(fmaxf(f.x, 0.f), fmaxf(f.y, 0.f));
}

// ---------- kernel 1: per-block stats partials (plain stores, high parallelism) ----------
__global__ void __launch_bounds__(128) prologue_kernel(const float* __restrict__ x)
{
    __shared__ float t[16][27];
    __shared__ float ps[4][32], pq[4][32], pmn[4][32], pmx[4][32];
    const int tid  = threadIdx.x;
    const int blk  = blockIdx.x;
    const int base = blk * 16;

    #pragma unroll
    for (int i = tid; i < 16 * L_SZ; i += 128) {
        int r = i / L_SZ, c = i - r * L_SZ;
        t[r][c] = x[base * L_SZ + i];
    }
    __syncthreads();

    {
        const int c = tid & 31, g = tid >> 5;
        float s = 0.f, q = 0.f, mn = 3.0e38f, mx = -3.0e38f;
        if (c < L_SZ) {
            #pragma unroll
            for (int r = g; r < 16; r += 4) {
                float v = t[r][c];
                s += v;
                q = fmaf(v, v, q);
                mn = fminf(mn, v);
                mx = fmaxf(mx, v);
            }
        }
        ps[g][c] = s; pq[g][c] = q; pmn[g][c] = mn; pmx[g][c] = mx;
    }
    __syncthreads();
    if (tid < L_SZ) {
        g_part[0][tid][blk] = ps[0][tid] + ps[1][tid] + ps[2][tid] + ps[3][tid];
        g_part[1][tid][blk] = pq[0][tid] + pq[1][tid] + pq[2][tid] + pq[3][tid];
        g_part[2][tid][blk] = fminf(fminf(pmn[0][tid], pmn[1][tid]), fminf(pmn[2][tid], pmn[3][tid]));
        g_part[3][tid][blk] = fmaxf(fmaxf(pmx[0][tid], pmx[1][tid]), fmaxf(pmx[2][tid], pmx[3][tid]));
    }
}

// ---------- kernel 2: one warp per l reduces 512 partials, computes grid params ----------
__global__ void __launch_bounds__(800) lparam_kernel(
    const float* __restrict__ gamma, const float* __restrict__ bn_bias)
{
    const int l    = threadIdx.x >> 5;
    const int lane = threadIdx.x & 31;
    if (l >= L_SZ) return;

    float s = 0.f, q = 0.f, mn = 3.0e38f, mx = -3.0e38f;
    #pragma unroll
    for (int j = lane; j < NPBLK; j += 32) {
        s += g_part[0][l][j];
        q += g_part[1][l][j];
        mn = fminf(mn, g_part[2][l][j]);
        mx = fmaxf(mx, g_part[3][l][j]);
    }
    #pragma unroll
    for (int o = 16; o > 0; o >>= 1) {
        s  += __shfl_down_sync(0xFFFFFFFFu, s, o);
        q  += __shfl_down_sync(0xFFFFFFFFu, q, o);
        mn  = fminf(mn, __shfl_down_sync(0xFFFFFFFFu, mn, o));
        mx  = fmaxf(mx, __shfl_down_sync(0xFFFFFFFFu, mx, o));
    }
    if (lane == 0) {
        float mean = s * (1.f / (float)B_SZ);
        float var  = q * (1.f / (float)B_SZ) - mean * mean;
        float sc   = gamma[l] * rsqrtf(var + BN_EPS);
        float sh   = bn_bias[l] - mean * sc;
        float a1 = fmaf(sc, mn, sh), a2 = fmaf(sc, mx, sh);
        float xnmin = fminf(a1, a2), xnmax = fmaxf(a1, a2);
        float range = xnmax - xnmin;
        float inv_h = (float)NCELL / range;
        g_lpXmin[l] = xnmin;
        g_lpH[l]    = range / (float)NCELL;
        g_lpA[l]    = sc * inv_h;
        g_lpC[l]    = (sh - xnmin) * inv_h;
    }
}

// ---------- kernel 3: tabulate each net, padded layout [l][cell][32] ----------
__global__ void __launch_bounds__(128) build_kernel(
    const float* __restrict__ W1, const float* __restrict__ b1,
    const float* __restrict__ W2, const float* __restrict__ b2,
    const float* __restrict__ W3, const float* __restrict__ b3,
    const float* __restrict__ W4, const float* __restrict__ b4,
    const float* __restrict__ alpha)
{
    __shared__ __align__(16) u64 sw1[8], sb1[8], sw2[64], sb2[8], sw3[48], sb3[6], sw4[6];
    __shared__ u64 sb4;
    __shared__ float nodes[NCELL + 2];

    const int l = blockIdx.x, k = blockIdx.y, tid = threadIdx.x;
    const int nb = k * L_SZ + l;

    if (tid < 8)  sw1[tid] = dup2(W1[nb * 8 + tid]);
    if (tid < 8)  sb1[tid] = dup2(b1[nb * 8 + tid]);
    if (tid < 64) sw2[tid] = dup2(W2[nb * 64 + tid]);
    if (tid < 8)  sb2[tid] = dup2(b2[nb * 8 + tid]);
    if (tid < 48) sw3[tid] = dup2(W3[nb * 48 + tid]);
    if (tid < 6)  sb3[tid] = dup2(b3[nb * 6 + tid]);
    if (tid < 6)  sw4[tid] = dup2(W4[nb * 6 + tid]);
    if (tid == 0) sb4 = dup2(b4[nb]);
    __syncthreads();

    const float xnmin = g_lpXmin[l];
    const float h     = g_lpH[l];

    // evaluate node pairs (2i, 2i+1), packed f32x2
    for (int i = tid; i < NCELL / 2 + 1; i += 128) {
        float x0 = fmaf((float)(2 * i), h, xnmin);
        u64 xn = pack2(x0, x0 + h);

        u64 h1[8];
        #pragma unroll
        for (int j = 0; j < 8; ++j) h1[j] = relu2(ffma2(xn, sw1[j], sb1[j]));
        u64 h2[8];
        #pragma unroll
        for (int j = 0; j < 8; ++j) {
            u64 a = sb2[j];
            #pragma unroll
            for (int q = 0; q < 8; ++q) a = ffma2(h1[q], sw2[j * 8 + q], a);
            h2[j] = relu2(a);
        }
        u64 h3[6];
        #pragma unroll
        for (int j = 0; j < 6; ++j) {
            u64 a = sb3[j];
            #pragma unroll
            for (int q = 0; q < 8; ++q) a = ffma2(h2[q], sw3[j * 8 + q], a);
            h3[j] = relu2(a);
        }
        u64 f = sb4;
        #pragma unroll
        for (int j = 0; j < 6; ++j) f = ffma2(h3[j], sw4[j], f);

        float2 fv = unpack2(f);
        int n0 = 2 * i;
        if (n0 <= NCELL)     nodes[n0] = fv.x;
        if (n0 + 1 <= NCELL) nodes[n0 + 1] = fv.y;
    }
    __syncthreads();

    const float al = alpha[l * K_SZ + k];
    for (int i = tid; i < NCELL; i += 128) {
        float f0 = nodes[i], f1 = nodes[i + 1];
        g_table[((l * NCELL + i) << 5) + k] = make_float2(al * f0, al * (f1 - f0));
    }
}

// ---------- kernel 4: warp-per-sample eval, shuffle precomputed offset+frac ----------
__global__ void __launch_bounds__(128) eval_kernel(
    const float* __restrict__ x,
    const float* __restrict__ beta, float* __restrict__ out)
{
    const int tid  = threadIdx.x;
    const int lane = tid & 31;
    const int warp = tid >> 5;
    const int b    = blockIdx.x * 4 + warp;       // one sample per warp

    // lane l owns feature l: compute its table offset + frac once
    int   off_own  = 0;
    float frac_own = 0.f;
    if (lane < L_SZ) {
        float u = fmaf(x[b * L_SZ + lane], g_lpA[lane], g_lpC[lane]);
        int idx = __float2int_rd(u);
        idx = min(max(idx, 0), NCELL - 1);
        frac_own = u - (float)idx;
        off_own  = (lane * NCELL + idx) << 5;     // padded stride 32
    }

    float acc0 = (lane < K_SZ) ? beta[lane] : 0.f;
    float acc1 = 0.f, acc2 = 0.f, acc3 = 0.f;

    #pragma unroll
    for (int l = 0; l < L_SZ; ++l) {
        int   off  = __shfl_sync(0xFFFFFFFFu, off_own, l);
        float frac = __shfl_sync(0xFFFFFFFFu, frac_own, l);
        if (lane < K_SZ) {
            float2 td = g_table[off + lane];      // 256B-aligned row: 2 wavefronts
            float v = fmaf(frac, td.y, td.x);
            if ((l & 3) == 0) acc0 += v;
            else if ((l & 3) == 1) acc1 += v;
            else if ((l & 3) == 2) acc2 += v;
            else acc3 += v;
        }
    }

    if (lane < K_SZ) out[b * K_SZ + lane] = ((acc0 + acc1) + (acc2 + acc3));
}

extern "C" void kernel_launch(void* const* d_in, const int* in_sizes, int n_in,
                              void* d_out, int out_size) {
    const float* x      = (const float*)d_in[0];
    const float* gamma  = (const float*)d_in[1];
    const float* bnb    = (const float*)d_in[2];
    const float* W1     = (const float*)d_in[3];
    const float* b1     = (const float*)d_in[4];
    const float* W2     = (const float*)d_in[5];
    const float* b2     = (const float*)d_in[6];
    const float* W3     = (const float*)d_in[7];
    const float* b3     = (const float*)d_in[8];
    const float* W4     = (const float*)d_in[9];
    const float* b4     = (const float*)d_in[10];
    const float* alpha  = (const float*)d_in[11];
    const float* beta   = (const float*)d_in[12];
    float* out = (float*)d_out;

    prologue_kernel<<<NPBLK, 128>>>(x);
    lparam_kernel<<<1, 800>>>(gamma, bnb);
    build_kernel<<<dim3(L_SZ, K_SZ), 128>>>(W1, b1, W2, b2, W3, b3, W4, b4, alpha);
    eval_kernel<<<B_SZ / 4, 128>>>(x, beta, out);
}